// round 3
// baseline (speedup 1.0000x reference)
#include <cuda_runtime.h>
#include <cstdint>

#define DSPIN 64
#define NPAIR (DSPIN * (DSPIN - 1) / 2)   // 2016
#define TPB 128
#define WPB (TPB / 32)
#define USTRIDE 17                         // 16 cols + 1 pad (odd -> conflict-free LDS)

// ---------- packed f32x2 helpers (sm_100+ PTX) ----------
static __device__ __forceinline__ unsigned long long pack2(float lo, float hi) {
    unsigned long long r;
    asm("mov.b64 %0, {%1, %2};" : "=l"(r) : "f"(lo), "f"(hi));
    return r;
}
static __device__ __forceinline__ void unpack2(unsigned long long v, float& lo, float& hi) {
    asm("mov.b64 {%0, %1}, %2;" : "=f"(lo), "=f"(hi) : "l"(v));
}
static __device__ __forceinline__ unsigned long long fma2(unsigned long long a,
                                                          unsigned long long b,
                                                          unsigned long long c) {
    unsigned long long d;
    asm("fma.rn.f32x2 %0, %1, %2, %3;" : "=l"(d) : "l"(a), "l"(b), "l"(c));
    return d;
}
static __device__ __forceinline__ unsigned long long add2(unsigned long long a,
                                                          unsigned long long b) {
    unsigned long long d;
    asm("add.rn.f32x2 %0, %1, %2;" : "=l"(d) : "l"(a), "l"(b));
    return d;
}

__global__ void __launch_bounds__(TPB, 3)
ising_kernel(const float* __restrict__ Q,
             const float* __restrict__ delta,
             const float* __restrict__ x0,
             const float* __restrict__ u,
             const int* __restrict__ cptr,
             float* __restrict__ out,
             int B, int L, int write_energy)
{
    __shared__ __align__(16) float Ms[DSPIN * DSPIN];   // 16 KB
    __shared__ float ds[DSPIN];
    // per-warp double-buffered u tile: 32 rows x 16 cols (stride 17)
    __shared__ float ubuf[WPB][2][32 * USTRIDE];        // ~17.4 KB

    const int tid  = threadIdx.x;
    const int lane = tid & 31;
    const int wid  = tid >> 5;

    // ---- build M in shared ----
    for (int i = tid; i < DSPIN * DSPIN; i += TPB) Ms[i] = 0.0f;
    if (tid < DSPIN) ds[tid] = delta[tid];
    __syncthreads();
    for (int p = tid; p < NPAIR; p += TPB) {
        int r = (int)((1.0f + sqrtf(8.0f * (float)p + 1.0f)) * 0.5f);
        while (r * (r - 1) / 2 > p) --r;
        while ((r + 1) * r / 2 <= p) ++r;
        int c = p - r * (r - 1) / 2;
        float q = Q[p];
        Ms[r * DSPIN + c] = q;
        Ms[c * DSPIN + r] = q;
    }
    __syncthreads();

    const int b  = blockIdx.x * TPB + tid;
    const int b0 = blockIdx.x * TPB + (wid << 5);   // warp's first row
    if (b >= B) return;

    const float cc = (float)(*cptr);

    // coalesced-load lane mapping for u chunks: lane j -> rows 8t+(j>>2), cols 4(j&3)..+3
    const int lrow = lane >> 2;          // 0..7
    const int lcol = (lane & 3) << 2;    // 0,4,8,12

    // ---- spins in registers, packed as 32 f32x2 values ----
    unsigned long long xp[DSPIN / 2];
    {
        const float4* x0r = reinterpret_cast<const float4*>(x0 + (size_t)b * DSPIN);
        #pragma unroll
        for (int i = 0; i < DSPIN / 4; ++i) {
            float4 v = __ldg(x0r + i);
            xp[2 * i]     = pack2(v.x, v.y);
            xp[2 * i + 1] = pack2(v.z, v.w);
        }
    }

    // ---- L Gauss-Seidel sweeps ----
    for (int l = 0; l < L; ++l) {
        const float* ub = u + ((size_t)l * B + b0) * DSPIN;

        float4 pre[4];
        #pragma unroll
        for (int t = 0; t < 4; ++t)   // prefetch chunk 0 (cols 0..15), coalesced
            pre[t] = __ldg(reinterpret_cast<const float4*>(
                         ub + (size_t)(8 * t + lrow) * DSPIN + lcol));

        #pragma unroll
        for (int c = 0; c < 4; ++c) {
            float* buf = ubuf[wid][c & 1];
            #pragma unroll
            for (int t = 0; t < 4; ++t) {       // 16 scalar STS, ~2-way conflicts
                int r = 8 * t + lrow;
                buf[r * USTRIDE + lcol + 0] = pre[t].x;
                buf[r * USTRIDE + lcol + 1] = pre[t].y;
                buf[r * USTRIDE + lcol + 2] = pre[t].z;
                buf[r * USTRIDE + lcol + 3] = pre[t].w;
            }
            if (c < 3) {
                const float* nb = ub + (c + 1) * 16;
                #pragma unroll
                for (int t = 0; t < 4; ++t)
                    pre[t] = __ldg(reinterpret_cast<const float4*>(
                                 nb + (size_t)(8 * t + lrow) * DSPIN + lcol));
            }
            __syncwarp();

            #pragma unroll
            for (int kk = 0; kk < 16; ++kk) {
                const int k = c * 16 + kk;
                const ulonglong2* Mr = reinterpret_cast<const ulonglong2*>(Ms + (k << 6));
                unsigned long long a0 = 0ull, a1 = 0ull, a2 = 0ull, a3 = 0ull;
                #pragma unroll
                for (int q = 0; q < DSPIN / 4; ++q) {
                    ulonglong2 m = Mr[q];
                    if (q & 1) {
                        a2 = fma2(m.x, xp[2 * q], a2);
                        a3 = fma2(m.y, xp[2 * q + 1], a3);
                    } else {
                        a0 = fma2(m.x, xp[2 * q], a0);
                        a1 = fma2(m.y, xp[2 * q + 1], a1);
                    }
                }
                unsigned long long s = add2(add2(a0, a2), add2(a1, a3));
                float slo, shi;
                unpack2(s, slo, shi);
                float alpha = ds[k] + slo + shi;     // M[k,k]==0

                float uk = buf[lane * USTRIDE + kk]; // conflict-free LDS
                float e1 = __expf(-2.0f * alpha);
                float sg = __fdividef(1.0f, 1.0f + e1);
                float y  = cc * (sg - uk);
                float e2 = __expf(-2.0f * fabsf(y));
                float t  = __fdividef(1.0f - e2, 1.0f + e2);
                float nx = copysignf(t, y);

                float lo, hi;
                unpack2(xp[k >> 1], lo, hi);
                if (k & 1) hi = nx; else lo = nx;
                xp[k >> 1] = pack2(lo, hi);
            }
        }
    }

    // ---- energy = sum_k (0.5*(z@M)[k] + delta[k]) * z[k] ----
    float energy = 0.0f;
    #pragma unroll
    for (int k = 0; k < DSPIN; ++k) {
        const ulonglong2* Mr = reinterpret_cast<const ulonglong2*>(Ms + (k << 6));
        unsigned long long a0 = 0ull, a1 = 0ull, a2 = 0ull, a3 = 0ull;
        #pragma unroll
        for (int q = 0; q < DSPIN / 4; ++q) {
            ulonglong2 m = Mr[q];
            if (q & 1) {
                a2 = fma2(m.x, xp[2 * q], a2);
                a3 = fma2(m.y, xp[2 * q + 1], a3);
            } else {
                a0 = fma2(m.x, xp[2 * q], a0);
                a1 = fma2(m.y, xp[2 * q + 1], a1);
            }
        }
        unsigned long long s = add2(add2(a0, a2), add2(a1, a3));
        float slo, shi;
        unpack2(s, slo, shi);
        float tk = slo + shi;
        float lo, hi;
        unpack2(xp[k >> 1], lo, hi);
        float xk = (k & 1) ? hi : lo;
        energy = fmaf(0.5f * tk + ds[k], xk, energy);
    }

    // ---- write z (B x 64) then energy (B) ----
    float4* zrow = reinterpret_cast<float4*>(out + (size_t)b * DSPIN);
    #pragma unroll
    for (int i = 0; i < DSPIN / 4; ++i) {
        float4 v;
        unpack2(xp[2 * i], v.x, v.y);
        unpack2(xp[2 * i + 1], v.z, v.w);
        zrow[i] = v;
    }
    if (write_energy) out[(size_t)B * DSPIN + b] = energy;
}

extern "C" void kernel_launch(void* const* d_in, const int* in_sizes, int n_in,
                              void* d_out, int out_size)
{
    // metadata order: inputs, Q, delta, x0, u, n_layers, const
    const float* Q     = (const float*)d_in[1];
    const float* delta = (const float*)d_in[2];
    const float* x0    = (const float*)d_in[3];
    const float* u     = (const float*)d_in[4];
    const int*   cptr  = (const int*)d_in[6];

    const int B = in_sizes[3] / DSPIN;
    const int L = (int)((long long)in_sizes[4] / ((long long)B * DSPIN));
    const int write_energy = (out_size >= B * DSPIN + B) ? 1 : 0;

    dim3 grid((B + TPB - 1) / TPB);
    ising_kernel<<<grid, TPB>>>(Q, delta, x0, u, cptr, (float*)d_out,
                                B, L, write_energy);
}

// round 5
// speedup vs baseline: 1.8392x; 1.8392x over previous
#include <cuda_runtime.h>
#include <cstdint>

#define DSPIN 64
#define NPAIR (DSPIN * (DSPIN - 1) / 2)   // 2016
#define TPB 128

// ---------- packed f32x2 helpers (sm_100+ PTX) ----------
static __device__ __forceinline__ unsigned long long pack2(float lo, float hi) {
    unsigned long long r;
    asm("mov.b64 %0, {%1, %2};" : "=l"(r) : "f"(lo), "f"(hi));
    return r;
}
static __device__ __forceinline__ void unpack2(unsigned long long v, float& lo, float& hi) {
    asm("mov.b64 {%0, %1}, %2;" : "=f"(lo), "=f"(hi) : "l"(v));
}
static __device__ __forceinline__ unsigned long long fma2(unsigned long long a,
                                                          unsigned long long b,
                                                          unsigned long long c) {
    unsigned long long d;
    asm("fma.rn.f32x2 %0, %1, %2, %3;" : "=l"(d) : "l"(a), "l"(b), "l"(c));
    return d;
}
static __device__ __forceinline__ unsigned long long add2(unsigned long long a,
                                                          unsigned long long b) {
    unsigned long long d;
    asm("add.rn.f32x2 %0, %1, %2;" : "=l"(d) : "l"(a), "l"(b));
    return d;
}

__global__ void __launch_bounds__(TPB, 2)
ising_kernel(const float* __restrict__ Q,
             const float* __restrict__ delta,
             const float* __restrict__ x0,
             const float* __restrict__ u,
             const int* __restrict__ cptr,
             float* __restrict__ out,
             int B, int L, int write_energy)
{
    __shared__ __align__(16) float Ms[DSPIN * DSPIN];   // 16 KB
    __shared__ float ds[DSPIN];

    const int tid = threadIdx.x;

    // ---- build symmetrized M in shared ----
    for (int i = tid; i < DSPIN * DSPIN; i += TPB) Ms[i] = 0.0f;
    if (tid < DSPIN) ds[tid] = delta[tid];
    __syncthreads();
    for (int p = tid; p < NPAIR; p += TPB) {
        int r = (int)((1.0f + sqrtf(8.0f * (float)p + 1.0f)) * 0.5f);
        while (r * (r - 1) / 2 > p) --r;
        while ((r + 1) * r / 2 <= p) ++r;
        int c = p - r * (r - 1) / 2;
        float q = Q[p];
        Ms[r * DSPIN + c] = q;
        Ms[c * DSPIN + r] = q;
    }
    __syncthreads();

    const int b = blockIdx.x * TPB + tid;
    if (b >= B) return;

    const float cc = (float)(*cptr);

    // ---- spins in registers, packed as 32 f32x2 values ----
    unsigned long long xp[DSPIN / 2];
    {
        const float4* x0r = reinterpret_cast<const float4*>(x0 + (size_t)b * DSPIN);
        #pragma unroll
        for (int i = 0; i < DSPIN / 4; ++i) {
            float4 v = __ldg(x0r + i);
            xp[2 * i]     = pack2(v.x, v.y);
            xp[2 * i + 1] = pack2(v.z, v.w);
        }
    }

    // ---- L Gauss-Seidel sweeps ----
    for (int l = 0; l < L; ++l) {
        const float4* urow = reinterpret_cast<const float4*>(u + ((size_t)l * B + b) * DSPIN);

        // one float4 (4 u values) per 4 k's, single-chunk-ahead prefetch
        float4 cur = __ldg(urow);
        #pragma unroll
        for (int c = 0; c < DSPIN / 4; ++c) {
            float4 nxt;
            if (c < DSPIN / 4 - 1) nxt = __ldg(urow + c + 1);

            #pragma unroll
            for (int j = 0; j < 4; ++j) {
                const int k = c * 4 + j;
                const ulonglong2* Mr = reinterpret_cast<const ulonglong2*>(Ms + (k << 6));
                unsigned long long a0 = 0ull, a1 = 0ull, a2 = 0ull, a3 = 0ull;
                #pragma unroll
                for (int q = 0; q < DSPIN / 4; ++q) {   // 16 x (LDS.128 + 2 FFMA2)
                    ulonglong2 m = Mr[q];
                    if (q & 1) {
                        a2 = fma2(m.x, xp[2 * q], a2);
                        a3 = fma2(m.y, xp[2 * q + 1], a3);
                    } else {
                        a0 = fma2(m.x, xp[2 * q], a0);
                        a1 = fma2(m.y, xp[2 * q + 1], a1);
                    }
                }
                unsigned long long s = add2(add2(a0, a2), add2(a1, a3));
                float slo, shi;
                unpack2(s, slo, shi);
                float alpha = ds[k] + slo + shi;        // M[k,k]==0

                float uk = (j & 2) ? ((j & 1) ? cur.w : cur.z)
                                   : ((j & 1) ? cur.y : cur.x);

                float e1 = __expf(-2.0f * alpha);
                float sg = __fdividef(1.0f, 1.0f + e1);
                float y  = cc * (sg - uk);
                float e2 = __expf(-2.0f * fabsf(y));
                float t  = __fdividef(1.0f - e2, 1.0f + e2);
                float nx = copysignf(t, y);

                float lo, hi;
                unpack2(xp[k >> 1], lo, hi);
                if (k & 1) hi = nx; else lo = nx;
                xp[k >> 1] = pack2(lo, hi);
            }

            if (c < DSPIN / 4 - 1) cur = nxt;
        }
    }

    // ---- energy = sum_k (0.5*(z@M)[k] + delta[k]) * z[k] ----
    float energy = 0.0f;
    #pragma unroll
    for (int k = 0; k < DSPIN; ++k) {
        const ulonglong2* Mr = reinterpret_cast<const ulonglong2*>(Ms + (k << 6));
        unsigned long long a0 = 0ull, a1 = 0ull, a2 = 0ull, a3 = 0ull;
        #pragma unroll
        for (int q = 0; q < DSPIN / 4; ++q) {
            ulonglong2 m = Mr[q];
            if (q & 1) {
                a2 = fma2(m.x, xp[2 * q], a2);
                a3 = fma2(m.y, xp[2 * q + 1], a3);
            } else {
                a0 = fma2(m.x, xp[2 * q], a0);
                a1 = fma2(m.y, xp[2 * q + 1], a1);
            }
        }
        unsigned long long s = add2(add2(a0, a2), add2(a1, a3));
        float slo, shi;
        unpack2(s, slo, shi);
        float tk = slo + shi;
        float lo, hi;
        unpack2(xp[k >> 1], lo, hi);
        float xk = (k & 1) ? hi : lo;
        energy = fmaf(0.5f * tk + ds[k], xk, energy);
    }

    // ---- write z (B x 64) then energy (B) ----
    float4* zrow = reinterpret_cast<float4*>(out + (size_t)b * DSPIN);
    #pragma unroll
    for (int i = 0; i < DSPIN / 4; ++i) {
        float4 v;
        unpack2(xp[2 * i], v.x, v.y);
        unpack2(xp[2 * i + 1], v.z, v.w);
        zrow[i] = v;
    }
    if (write_energy) out[(size_t)B * DSPIN + b] = energy;
}

extern "C" void kernel_launch(void* const* d_in, const int* in_sizes, int n_in,
                              void* d_out, int out_size)
{
    // metadata order: inputs, Q, delta, x0, u, n_layers, const
    const float* Q     = (const float*)d_in[1];
    const float* delta = (const float*)d_in[2];
    const float* x0    = (const float*)d_in[3];
    const float* u     = (const float*)d_in[4];
    const int*   cptr  = (const int*)d_in[6];

    const int B = in_sizes[3] / DSPIN;
    const int L = (int)((long long)in_sizes[4] / ((long long)B * DSPIN));
    const int write_energy = (out_size >= B * DSPIN + B) ? 1 : 0;

    dim3 grid((B + TPB - 1) / TPB);
    ising_kernel<<<grid, TPB>>>(Q, delta, x0, u, cptr, (float*)d_out,
                                B, L, write_energy);
}